// round 15
// baseline (speedup 1.0000x reference)
#include <cuda_runtime.h>
#include <cuda_fp16.h>
#include <cstdint>
#include <cstddef>

// Fused e3nn per-irrep linear, fp16 mma.sync m16n8k16 + fp32 accum.
// R15: CUTLASS-shape tiles to cut SMEM wavefronts per mma ~1.45x:
// CTA 128x256x32 (warp 64x64, acc=128) for D=1; 96x256 (warp 48x64) for D=3;
// 80x256 (warp 80x32, NWM=1) for D=5. 8 warps, 1 CTA/SM, 255-reg budget.
//   out[b, off + w*D + i] = PW * sum_u W[u,w] * x[b, off + u*D + i]  (+bias, D==1)

static constexpr int MUL   = 512;
static constexpr int DIM   = 4608;
static constexpr int BATCH = 4096;
static constexpr int BN  = 256;
static constexpr int BK  = 32;
static constexpr int NKT = MUL / BK;          // 16 k-tiles
static constexpr float PW = 0.04419417382415922f;  // folded into wT2

static constexpr int LDA   = 80;              // A row stride bytes
static constexpr int LDB   = 80;              // B n-row stride bytes
static constexpr int A_REG = 128 * LDA;       // 10240 (max R=128)
static constexpr int B_REG = BN * LDB;        // 20480
static constexpr int STAGE = A_REG + B_REG;   // 30720
static constexpr int NSTG  = 4;
static constexpr int SM_TOTAL = NSTG * STAGE; // 122880 B -> 1 CTA/SM
static constexpr int CSTR  = 264;             // C-stage stride (floats): 2-way max

static constexpr int X2_R1 = 0;
static constexpr int X2_R3 = 4096;
static constexpr int X2_R5 = 4096 + 12288;
__device__ __half x2_buf[36864 * MUL];
__device__ __half wT2_buf[3 * MUL * MUL];     // n-major, PW-prescaled fp16

__device__ __forceinline__ void cp16(uint32_t s, const void* g) {
    asm volatile("cp.async.cg.shared.global [%0], [%1], 16;" :: "r"(s), "l"(g));
}
__device__ __forceinline__ void cp_commit() {
    asm volatile("cp.async.commit_group;" ::: "memory");
}
__device__ __forceinline__ void cp_wait2() {
    asm volatile("cp.async.wait_group 2;" ::: "memory");
}
__device__ __forceinline__ void ldmx4(uint32_t& r0, uint32_t& r1, uint32_t& r2,
                                      uint32_t& r3, uint32_t addr) {
    asm volatile("ldmatrix.sync.aligned.m8n8.x4.shared.b16 {%0,%1,%2,%3}, [%4];"
                 : "=r"(r0), "=r"(r1), "=r"(r2), "=r"(r3) : "r"(addr));
}
__device__ __forceinline__ void mma_f16(
    float& c0, float& c1, float& c2, float& c3,
    uint32_t a0, uint32_t a1, uint32_t a2, uint32_t a3,
    uint32_t b0, uint32_t b1)
{
    asm volatile(
        "mma.sync.aligned.m16n8k16.row.col.f32.f16.f16.f32 "
        "{%0,%1,%2,%3}, {%4,%5,%6,%7}, {%8,%9}, {%0,%1,%2,%3};"
        : "+f"(c0), "+f"(c1), "+f"(c2), "+f"(c3)
        : "r"(a0), "r"(a1), "r"(a2), "r"(a3), "r"(b0), "r"(b1));
}

// ---- merged pre-pass (288 threads): convert x warp-per-row + transpose W ----
__global__ void prep_kernel(const float* __restrict__ x,
                            const float* __restrict__ w0,
                            const float* __restrict__ w1,
                            const float* __restrict__ w2)
{
    __shared__ float buf[DIM];
    const int tid = threadIdx.x;
    if (blockIdx.x < BATCH) {
        const int b = blockIdx.x;
        const float* src = x + (size_t)b * DIM;
        #pragma unroll
        for (int v = tid; v < DIM / 4; v += 288)
            *reinterpret_cast<float4*>(&buf[v * 4]) =
                reinterpret_cast<const float4*>(src)[v];
        __syncthreads();
        const int w    = tid >> 5;
        const int lane = tid & 31;
        int off, D, grow;
        if (w == 0)      { off = 0;            D = 1; grow = X2_R1 + b; }
        else if (w < 4)  { off = 512 + (w-1);  D = 3; grow = X2_R3 + b * 3 + (w-1); }
        else             { off = 2048 + (w-4); D = 5; grow = X2_R5 + b * 5 + (w-4); }
        __half2* dst = reinterpret_cast<__half2*>(x2_buf + (size_t)grow * MUL);
        #pragma unroll
        for (int q = 0; q < 8; q++) {
            const int c2 = lane + q * 32;
            const float lo = buf[off + (2 * c2    ) * D];
            const float hi = buf[off + (2 * c2 + 1) * D];
            dst[c2] = __floats2half2_rn(lo, hi);
        }
    } else {
        const int tb = blockIdx.x - BATCH;
        const int m  = tb >> 8;
        const int r  = tb & 255;
        const int kb = (r >> 4) * 32, nb = (r & 15) * 32;
        const float* src = (m == 0) ? w0 : (m == 1) ? w1 : w2;
        __half* dst = wT2_buf + m * MUL * MUL;
        float (*tile)[33] = reinterpret_cast<float(*)[33]>(buf);
        const int tx = tid & 31, ty = tid >> 5;
        for (int i = ty; i < 32; i += 9)
            tile[i][tx] = src[(size_t)(kb + i) * MUL + nb + tx];
        __syncthreads();
        for (int i = ty; i < 32; i += 9)
            dst[(size_t)(nb + i) * MUL + kb + tx] =
                __float2half_rn(tile[tx][i] * PW);
    }
}

template<int D, int R, int NWM, int NWN>
__device__ __forceinline__ void run_tile(
    const __half* __restrict__ x2, const __half* __restrict__ wT,
    const float* __restrict__ bias, float* __restrict__ out,
    int mt, int nt, int off, uint32_t smb, float* smf)
{
    constexpr int WM    = R / NWM;
    constexpr int WN    = BN / NWN;
    constexpr int MFRAG = WM / 16;
    constexpr int NFRAG = WN / 8;
    constexpr int ACH   = R * 4;                // 16B A chunks per stage
    constexpr int NAE   = (ACH + 255) / 256;
    constexpr int NBE   = BN * 4 / 256;         // 4
    static_assert(NWM * NWN == 8 && WM % 16 == 0 && NFRAG % 2 == 0, "layout");

    const int tid  = threadIdx.x;
    const int wid  = tid >> 5;
    const int lane = tid & 31;
    const int g    = lane >> 2;
    const int tig  = lane & 3;
    const int wm   = wid % NWM;
    const int wn   = wid / NWM;
    const int rt0  = mt * R;
    const int w0   = nt * BN;

    const __half* const xb = x2 + (size_t)rt0 * MUL;
    const __half* aptrg[NAE];
    uint32_t      aoffs[NAE];
    bool          aval [NAE];
    #pragma unroll
    for (int e = 0; e < NAE; e++) {
        const int v = tid + e * 256;
        const int r = v >> 2, kq = v & 3;
        aval[e]  = (v < ACH);
        aptrg[e] = xb + (size_t)r * MUL + kq * 8;
        aoffs[e] = (uint32_t)(r * LDA + kq * 16);
    }
    const __half* const wb = wT + (size_t)w0 * MUL;
    const __half* bptrg[NBE];
    uint32_t      boffs[NBE];
    #pragma unroll
    for (int e = 0; e < NBE; e++) {
        const int v = tid + e * 256;
        const int n = v >> 2, kq = v & 3;
        bptrg[e] = wb + (size_t)n * MUL + kq * 8;
        boffs[e] = (uint32_t)(A_REG + n * LDB + kq * 16);
    }
    const int a_row = (lane & 7) + ((lane >> 3) & 1) * 8;
    const int a_kh  = (lane >> 4) * 16;
    const uint32_t a_lm = (uint32_t)((wm * WM + a_row) * LDA + a_kh);
    const int b_row = (lane & 7) + (lane >> 4) * 8;
    const int b_kh  = ((lane >> 3) & 1) * 16;
    const uint32_t b_lm = (uint32_t)(A_REG + (wn * WN + b_row) * LDB + b_kh);

    float acc[MFRAG][NFRAG][4] = {};

    uint32_t stg[NSTG];
    #pragma unroll
    for (int s = 0; s < NSTG; s++) stg[s] = smb + s * STAGE;

    auto load_tile = [&](int t, uint32_t base) {
        const int tk = t * BK;
        #pragma unroll
        for (int e = 0; e < NAE; e++)
            if (aval[e]) cp16(base + aoffs[e], aptrg[e] + tk);
        #pragma unroll
        for (int e = 0; e < NBE; e++)
            cp16(base + boffs[e], bptrg[e] + tk);
    };

    load_tile(0, stg[0]); cp_commit();
    load_tile(1, stg[1]); cp_commit();
    load_tile(2, stg[2]); cp_commit();

    for (int t = 0; t < NKT; t++) {
        cp_wait2();
        __syncthreads();
        if (t + 3 < NKT) load_tile(t + 3, stg[(t + 3) & 3]);
        cp_commit();

        const uint32_t Ac = stg[t & 3];
        #pragma unroll
        for (int s = 0; s < 2; s++) {
            uint32_t afr[MFRAG][4];
            #pragma unroll
            for (int m = 0; m < MFRAG; m++)
                ldmx4(afr[m][0], afr[m][1], afr[m][2], afr[m][3],
                      Ac + a_lm + (uint32_t)(m * 16 * LDA + s * 32));
            uint32_t bfr[NFRAG][2];
            #pragma unroll
            for (int j = 0; j < NFRAG; j += 2)
                ldmx4(bfr[j][0], bfr[j][1], bfr[j + 1][0], bfr[j + 1][1],
                      Ac + b_lm + (uint32_t)(j * 8 * LDB + s * 32));
            #pragma unroll
            for (int m = 0; m < MFRAG; m++)
                #pragma unroll
                for (int n = 0; n < NFRAG; n++)
                    mma_f16(acc[m][n][0], acc[m][n][1], acc[m][n][2], acc[m][n][3],
                            afr[m][0], afr[m][1], afr[m][2], afr[m][3],
                            bfr[n][0], bfr[n][1]);
        }
    }

    if constexpr (D == 1) {
        // direct epilogue (off = 0, stride-1 in w, sectors covered by tig quads)
        #pragma unroll
        for (int m = 0; m < MFRAG; m++) {
            #pragma unroll
            for (int half = 0; half < 2; half++) {
                const int row = rt0 + wm * WM + m * 16 + g + half * 8;
                float* orow = out + (size_t)row * DIM;
                #pragma unroll
                for (int n = 0; n < NFRAG; n++) {
                    const int wc = w0 + wn * WN + n * 8 + 2 * tig;
                    float2 v;
                    v.x = acc[m][n][half * 2    ] + bias[wc];
                    v.y = acc[m][n][half * 2 + 1] + bias[wc + 1];
                    *reinterpret_cast<float2*>(orow + wc) = v;
                }
            }
        }
    } else {
        // SMEM-staged coalesced epilogue (C tile R*CSTR*4 <= 122880)
        __syncthreads();
        #pragma unroll
        for (int m = 0; m < MFRAG; m++) {
            #pragma unroll
            for (int half = 0; half < 2; half++) {
                const int r = wm * WM + m * 16 + g + half * 8;
                #pragma unroll
                for (int n = 0; n < NFRAG; n++) {
                    const int c = wn * WN + n * 8 + 2 * tig;
                    smf[r * CSTR + c    ] = acc[m][n][half * 2    ];
                    smf[r * CSTR + c + 1] = acc[m][n][half * 2 + 1];
                }
            }
        }
        __syncthreads();
        constexpr int TOT4 = R * BN / 4;
        const int bgl = rt0 / D;                 // R is a multiple of D
        for (int p4 = tid; p4 < TOT4; p4 += 256) {
            const int p   = p4 * 4;
            const int bl  = p / (BN * D);
            const int rem = p - bl * (BN * D);
            float tmp[4];
            #pragma unroll
            for (int j = 0; j < 4; j++) {
                const int rj = rem + j;
                tmp[j] = smf[(bl * D + rj % D) * CSTR + rj / D];
            }
            float* dst = out + (size_t)(bgl + bl) * DIM + off + w0 * D + rem;
            *reinterpret_cast<float4*>(dst) =
                make_float4(tmp[0], tmp[1], tmp[2], tmp[3]);
        }
    }
}

// D=1: 128x256 -> 32*2 = 64; D=3: 96x256 -> 128*2 = 256; D=5: 80x256 -> 256*2 = 512
static constexpr int NB0 = 32 * 2;
static constexpr int NB1 = 128 * 2;
static constexpr int NB2 = 256 * 2;

__global__ __launch_bounds__(256, 1) void fused_irrep_kernel(
    const float* __restrict__ b0, float* __restrict__ out)
{
    extern __shared__ __align__(16) char sm[];
    const uint32_t smb = (uint32_t)__cvta_generic_to_shared(sm);
    float* smf = reinterpret_cast<float*>(sm);
    const int bx = blockIdx.x;
    if (bx < NB0) {
        run_tile<1, 128, 2, 4>(x2_buf + (size_t)X2_R1 * MUL, wT2_buf,
                               b0, out, bx >> 1, bx & 1, 0, smb, smf);
    } else if (bx < NB0 + NB1) {
        const int i = bx - NB0;
        run_tile<3,  96, 2, 4>(x2_buf + (size_t)X2_R3 * MUL, wT2_buf + MUL * MUL,
                               b0, out, i >> 1, i & 1, 512, smb, smf);
    } else {
        const int i = bx - NB0 - NB1;
        run_tile<5,  80, 1, 8>(x2_buf + (size_t)X2_R5 * MUL, wT2_buf + 2 * MUL * MUL,
                               b0, out, i >> 1, i & 1, 2048, smb, smf);
    }
}

extern "C" void kernel_launch(void* const* d_in, const int* in_sizes, int n_in,
                              void* d_out, int out_size)
{
    const float* x  = (const float*)d_in[0];
    const float* w0 = (const float*)d_in[1];
    const float* w1 = (const float*)d_in[2];
    const float* w2 = (const float*)d_in[3];
    const float* b0 = (const float*)d_in[4];
    float* out = (float*)d_out;

    prep_kernel<<<BATCH + 768, 288>>>(x, w0, w1, w2);
    cudaFuncSetAttribute(fused_irrep_kernel,
                         cudaFuncAttributeMaxDynamicSharedMemorySize, SM_TOTAL);
    fused_irrep_kernel<<<NB0 + NB1 + NB2, 256, SM_TOTAL>>>(b0, out);
}

// round 16
// speedup vs baseline: 1.0208x; 1.0208x over previous
#include <cuda_runtime.h>
#include <cuda_fp16.h>
#include <cstdint>
#include <cstddef>

// Fused e3nn per-irrep linear, fp16 mma.sync m16n8k16 + fp32 accum.
// R16 = consolidation: R12's main GEMM (best measured: 78.9us) verbatim
//       + R14's warp-per-row prep kernel (best measured: ~22us incl gap).
//   out[b, off + w*D + i] = PW * sum_u W[u,w] * x[b, off + u*D + i]  (+bias, D==1)

static constexpr int MUL   = 512;
static constexpr int DIM   = 4608;
static constexpr int BATCH = 4096;
static constexpr int BN  = 128;
static constexpr int BK  = 32;
static constexpr int NKT = MUL / BK;          // 16 k-tiles
static constexpr float PW = 0.04419417382415922f;  // folded into wT2

static constexpr int LDA   = 80;
static constexpr int LDB   = 80;
static constexpr int A_REG = 160 * LDA;       // 12800 B (max R=160)
static constexpr int B_REG = BN * LDB;        // 10240 B
static constexpr int STAGE = A_REG + B_REG;   // 23040
static constexpr int NSTG  = 4;
static constexpr int SM_TOTAL = NSTG * STAGE; // 92160 B -> 2 CTAs/SM

static constexpr int X2_R1 = 0;
static constexpr int X2_R3 = 4096;
static constexpr int X2_R5 = 4096 + 12288;
__device__ __half x2_buf[36864 * MUL];
__device__ __half wT2_buf[3 * MUL * MUL];     // n-major, PW-prescaled fp16

__device__ __forceinline__ void cp16(uint32_t s, const void* g) {
    asm volatile("cp.async.cg.shared.global [%0], [%1], 16;" :: "r"(s), "l"(g));
}
__device__ __forceinline__ void cp_commit() {
    asm volatile("cp.async.commit_group;" ::: "memory");
}
__device__ __forceinline__ void cp_wait2() {
    asm volatile("cp.async.wait_group 2;" ::: "memory");
}
__device__ __forceinline__ void ldmx4(uint32_t& r0, uint32_t& r1, uint32_t& r2,
                                      uint32_t& r3, uint32_t addr) {
    asm volatile("ldmatrix.sync.aligned.m8n8.x4.shared.b16 {%0,%1,%2,%3}, [%4];"
                 : "=r"(r0), "=r"(r1), "=r"(r2), "=r"(r3) : "r"(addr));
}
__device__ __forceinline__ void mma_f16(
    float& c0, float& c1, float& c2, float& c3,
    uint32_t a0, uint32_t a1, uint32_t a2, uint32_t a3,
    uint32_t b0, uint32_t b1)
{
    asm volatile(
        "mma.sync.aligned.m16n8k16.row.col.f32.f16.f16.f32 "
        "{%0,%1,%2,%3}, {%4,%5,%6,%7}, {%8,%9}, {%0,%1,%2,%3};"
        : "+f"(c0), "+f"(c1), "+f"(c2), "+f"(c3)
        : "r"(a0), "r"(a1), "r"(a2), "r"(a3), "r"(b0), "r"(b1));
}

// ---- merged pre-pass (288 threads): convert x warp-per-row + transpose W ----
__global__ void prep_kernel(const float* __restrict__ x,
                            const float* __restrict__ w0,
                            const float* __restrict__ w1,
                            const float* __restrict__ w2)
{
    __shared__ float buf[DIM];
    const int tid = threadIdx.x;
    if (blockIdx.x < BATCH) {
        const int b = blockIdx.x;
        const float* src = x + (size_t)b * DIM;
        #pragma unroll
        for (int v = tid; v < DIM / 4; v += 288)
            *reinterpret_cast<float4*>(&buf[v * 4]) =
                reinterpret_cast<const float4*>(src)[v];
        __syncthreads();
        const int w    = tid >> 5;        // warp = output row j (0..8)
        const int lane = tid & 31;
        int off, D, grow;
        if (w == 0)      { off = 0;            D = 1; grow = X2_R1 + b; }
        else if (w < 4)  { off = 512 + (w-1);  D = 3; grow = X2_R3 + b * 3 + (w-1); }
        else             { off = 2048 + (w-4); D = 5; grow = X2_R5 + b * 5 + (w-4); }
        __half2* dst = reinterpret_cast<__half2*>(x2_buf + (size_t)grow * MUL);
        #pragma unroll
        for (int q = 0; q < 8; q++) {
            const int c2 = lane + q * 32;
            const float lo = buf[off + (2 * c2    ) * D];
            const float hi = buf[off + (2 * c2 + 1) * D];
            dst[c2] = __floats2half2_rn(lo, hi);
        }
    } else {
        const int tb = blockIdx.x - BATCH;
        const int m  = tb >> 8;
        const int r  = tb & 255;
        const int kb = (r >> 4) * 32, nb = (r & 15) * 32;
        const float* src = (m == 0) ? w0 : (m == 1) ? w1 : w2;
        __half* dst = wT2_buf + m * MUL * MUL;
        float (*tile)[33] = reinterpret_cast<float(*)[33]>(buf);
        const int tx = tid & 31, ty = tid >> 5;   // 32 x 9
        for (int i = ty; i < 32; i += 9)
            tile[i][tx] = src[(size_t)(kb + i) * MUL + nb + tx];
        __syncthreads();
        for (int i = ty; i < 32; i += 9)
            dst[(size_t)(nb + i) * MUL + kb + tx] =
                __float2half_rn(tile[tx][i] * PW);
    }
}

template<int D, int R, int NWM, int NWN>
__device__ __forceinline__ void run_tile(
    const __half* __restrict__ x2, const __half* __restrict__ wT,
    const float* __restrict__ bias, float* __restrict__ out,
    int mt, int nt, int off, uint32_t smb, float* smf)
{
    constexpr int WM    = R / NWM;
    constexpr int WN    = BN / NWN;
    constexpr int MFRAG = WM / 16;
    constexpr int NFRAG = WN / 8;
    constexpr int ACH   = R * 4;
    constexpr int NAE   = (ACH + 255) / 256;
    static_assert(NWM * NWN == 8 && WM % 16 == 0 && NFRAG % 2 == 0, "layout");

    const int tid  = threadIdx.x;
    const int wid  = tid >> 5;
    const int lane = tid & 31;
    const int g    = lane >> 2;
    const int tig  = lane & 3;
    const int wm   = wid % NWM;
    const int wn   = wid / NWM;
    const int rt0  = mt * R;
    const int w0   = nt * BN;

    const __half* const xb = x2 + (size_t)rt0 * MUL;
    const __half* aptrg[NAE];
    uint32_t      aoffs[NAE];
    bool          aval [NAE];
    #pragma unroll
    for (int e = 0; e < NAE; e++) {
        const int v = tid + e * 256;
        const int r = v >> 2, kq = v & 3;
        aval[e]  = (v < ACH);
        aptrg[e] = xb + (size_t)r * MUL + kq * 8;
        aoffs[e] = (uint32_t)(r * LDA + kq * 16);
    }
    const __half* const wb = wT + (size_t)w0 * MUL;
    const __half* bptrg[2];
    uint32_t      boffs[2];
    #pragma unroll
    for (int e = 0; e < 2; e++) {
        const int v = tid + e * 256;
        const int n = v >> 2, kq = v & 3;
        bptrg[e] = wb + (size_t)n * MUL + kq * 8;
        boffs[e] = (uint32_t)(A_REG + n * LDB + kq * 16);
    }
    const int a_row = (lane & 7) + ((lane >> 3) & 1) * 8;
    const int a_kh  = (lane >> 4) * 16;
    const uint32_t a_lm = (uint32_t)((wm * WM + a_row) * LDA + a_kh);
    const int b_row = (lane & 7) + (lane >> 4) * 8;
    const int b_kh  = ((lane >> 3) & 1) * 16;
    const uint32_t b_lm = (uint32_t)(A_REG + (wn * WN + b_row) * LDB + b_kh);

    float acc[MFRAG][NFRAG][4] = {};

    uint32_t stg[NSTG];
    #pragma unroll
    for (int s = 0; s < NSTG; s++) stg[s] = smb + s * STAGE;

    auto load_tile = [&](int t, uint32_t base) {
        const int tk = t * BK;
        #pragma unroll
        for (int e = 0; e < NAE; e++)
            if (aval[e]) cp16(base + aoffs[e], aptrg[e] + tk);
        #pragma unroll
        for (int e = 0; e < 2; e++)
            cp16(base + boffs[e], bptrg[e] + tk);
    };

    load_tile(0, stg[0]); cp_commit();
    load_tile(1, stg[1]); cp_commit();
    load_tile(2, stg[2]); cp_commit();

    const int s0 = wid & 1;              // warp-parity substep stagger
    for (int t = 0; t < NKT; t++) {
        cp_wait2();
        __syncthreads();
        if (t + 3 < NKT) load_tile(t + 3, stg[(t + 3) & 3]);
        cp_commit();

        const uint32_t Ac = stg[t & 3];
        #pragma unroll
        for (int si = 0; si < 2; si++) {
            const int s = si ^ s0;
            uint32_t afr[MFRAG][4];
            #pragma unroll
            for (int m = 0; m < MFRAG; m++)
                ldmx4(afr[m][0], afr[m][1], afr[m][2], afr[m][3],
                      Ac + a_lm + (uint32_t)(m * 16 * LDA + s * 32));
            uint32_t bfr[NFRAG][2];
            #pragma unroll
            for (int j = 0; j < NFRAG; j += 2)
                ldmx4(bfr[j][0], bfr[j][1], bfr[j + 1][0], bfr[j + 1][1],
                      Ac + b_lm + (uint32_t)(j * 8 * LDB + s * 32));
            #pragma unroll
            for (int m = 0; m < MFRAG; m++)
                #pragma unroll
                for (int n = 0; n < NFRAG; n++)
                    mma_f16(acc[m][n][0], acc[m][n][1], acc[m][n][2], acc[m][n][3],
                            afr[m][0], afr[m][1], afr[m][2], afr[m][3],
                            bfr[n][0], bfr[n][1]);
        }
    }

    // ---- epilogue: stage C in SMEM, coalesced STG.128 (PW already in wT2) ----
    __syncthreads();
    #pragma unroll
    for (int m = 0; m < MFRAG; m++) {
        #pragma unroll
        for (int half = 0; half < 2; half++) {
            const int r = wm * WM + m * 16 + g + half * 8;
            #pragma unroll
            for (int n = 0; n < NFRAG; n++) {
                const int c = wn * WN + n * 8 + 2 * tig;
                smf[r * 128 + c    ] = acc[m][n][half * 2    ];
                smf[r * 128 + c + 1] = acc[m][n][half * 2 + 1];
            }
        }
    }
    __syncthreads();

    constexpr int TOT4 = R * 128 / 4;
    const int bgl = rt0 / D;
    for (int p4 = tid; p4 < TOT4; p4 += 256) {
        const int p   = p4 * 4;
        const int bl  = p / (128 * D);
        const int rem = p - bl * (128 * D);
        float4 v;
        if constexpr (D == 1) {
            v = reinterpret_cast<const float4*>(smf)[p4];
            const float4 bb = *reinterpret_cast<const float4*>(bias + w0 + rem);
            v.x += bb.x; v.y += bb.y; v.z += bb.z; v.w += bb.w;
        } else {
            float tmp[4];
            #pragma unroll
            for (int j = 0; j < 4; j++) {
                const int rj = rem + j;
                tmp[j] = smf[(bl * D + rj % D) * 128 + rj / D];
            }
            v = make_float4(tmp[0], tmp[1], tmp[2], tmp[3]);
        }
        float* dst = out + (size_t)(bgl + bl) * DIM + off + w0 * D + rem;
        *reinterpret_cast<float4*>(dst) = v;
    }
}

// D=1: R=128 -> 32 mtiles; D=3: R=96 -> 128; D=5: R=160 -> 128. x4 ntiles.
static constexpr int NB0 = 32 * 4;
static constexpr int NB1 = 128 * 4;
static constexpr int NB2 = 128 * 4;

__global__ __launch_bounds__(256, 2) void fused_irrep_kernel(
    const float* __restrict__ b0, float* __restrict__ out)
{
    extern __shared__ __align__(16) char sm[];
    const uint32_t smb = (uint32_t)__cvta_generic_to_shared(sm);
    float* smf = reinterpret_cast<float*>(sm);
    const int bx = blockIdx.x;
    if (bx < NB0) {
        run_tile<1, 128, 2, 4>(x2_buf + (size_t)X2_R1 * MUL, wT2_buf,
                               b0, out, bx >> 2, bx & 3, 0, smb, smf);
    } else if (bx < NB0 + NB1) {
        const int i = bx - NB0;
        run_tile<3,  96, 2, 4>(x2_buf + (size_t)X2_R3 * MUL, wT2_buf + MUL * MUL,
                               b0, out, i >> 2, i & 3, 512, smb, smf);
    } else {
        const int i = bx - NB0 - NB1;
        run_tile<5, 160, 2, 4>(x2_buf + (size_t)X2_R5 * MUL, wT2_buf + 2 * MUL * MUL,
                               b0, out, i >> 2, i & 3, 2048, smb, smf);
    }
}

extern "C" void kernel_launch(void* const* d_in, const int* in_sizes, int n_in,
                              void* d_out, int out_size)
{
    const float* x  = (const float*)d_in[0];
    const float* w0 = (const float*)d_in[1];
    const float* w1 = (const float*)d_in[2];
    const float* w2 = (const float*)d_in[3];
    const float* b0 = (const float*)d_in[4];
    float* out = (float*)d_out;

    prep_kernel<<<BATCH + 768, 288>>>(x, w0, w1, w2);
    cudaFuncSetAttribute(fused_irrep_kernel,
                         cudaFuncAttributeMaxDynamicSharedMemorySize, SM_TOTAL);
    fused_irrep_kernel<<<NB0 + NB1 + NB2, 256, SM_TOTAL>>>(b0, out);
}